// round 5
// baseline (speedup 1.0000x reference)
#include <cuda_runtime.h>
#include <cuda_bf16.h>
#include <cstdint>

// Problem constants (fixed by the reference)
#define NSIDE 64
#define NPIX  (12 * NSIDE * NSIDE)   // 49152
#define B     8
#define C     16
#define NN    524288                 // N

#define BINS  (B * NPIX)             // 393216

// Scratch: per-(batch,pixel) {sum, count}, one v2 REDG updates both.
// Zero-initialized at module load; write_kernel restores zeros after reading
// (graph-replay safe, no zeroing kernel).
__device__ float2 g_bin[BINS];

__device__ __forceinline__ void red_v2(float2* p, float v) {
    asm volatile("red.global.add.v2.f32 [%0], {%1, %2};"
                 :: "l"(p), "f"(v), "f"(1.0f) : "memory");
}

// ---------------------------------------------------------------------------
// Pass 1: scatter-accumulate. 8 elements per thread: two float4/int4 load
// pairs issued up front (front-batched -> high MLP), then 8 v2 REDG atomics.
// vals layout [B, C, N] -> channel 0 of batch b starts at b*C*N.
// ---------------------------------------------------------------------------
__global__ void accum_kernel(const float* __restrict__ vals,
                             const int*   __restrict__ pix) {
    const int t = blockIdx.x * blockDim.x + threadIdx.x;  // 0 .. B*N/8-1
    const int per_batch = NN / 8;                 // 65536 vec8 per batch
    const int b = t / per_batch;
    const int v = t % per_batch;

    const float4* __restrict__ vp =
        reinterpret_cast<const float4*>(vals + (long long)b * C * NN);
    const int4* __restrict__ ip =
        reinterpret_cast<const int4*>(pix + (long long)b * NN);

    // front-batched loads (independent -> MLP=4)
    const float4 v0 = vp[2 * v + 0];
    const float4 v1 = vp[2 * v + 1];
    const int4   p0 = ip[2 * v + 0];
    const int4   p1 = ip[2 * v + 1];

    float2* __restrict__ bin = g_bin + b * NPIX;

    red_v2(bin + p0.x, v0.x);
    red_v2(bin + p0.y, v0.y);
    red_v2(bin + p0.z, v0.z);
    red_v2(bin + p0.w, v0.w);
    red_v2(bin + p1.x, v1.x);
    red_v2(bin + p1.y, v1.y);
    red_v2(bin + p1.z, v1.z);
    red_v2(bin + p1.w, v1.w);
}

// ---------------------------------------------------------------------------
// Pass 2: mean + broadcast over C=16, reset bins.
// Grid-stride, 4 float4-writes per thread. All 4 bin loads hoisted (MLP=4),
// fast reciprocal instead of FDIV (no slow-path), coalesced STG.128.
// Output layout [B, NPIX, C]: bin i owns out float4s [4i .. 4i+3].
// ---------------------------------------------------------------------------
#define W_THREADS (BINS)            // 393216 threads, 4 iterations each
#define W_ITERS   4

__global__ void write_kernel(float* __restrict__ out) {
    const int tid = blockIdx.x * blockDim.x + threadIdx.x;   // 0 .. W_THREADS-1
    const int S = W_THREADS;

    // hoisted independent bin loads
    float2 sc[W_ITERS];
#pragma unroll
    for (int k = 0; k < W_ITERS; k++) {
        sc[k] = g_bin[(tid + k * S) >> 2];
    }

    // self-clean: threads with tid%4==0 own the bin resets
    if ((tid & 3) == 0) {
#pragma unroll
        for (int k = 0; k < W_ITERS; k++) {
            g_bin[(tid + k * S) >> 2] = make_float2(0.f, 0.f);
        }
    }

    float4* __restrict__ o = reinterpret_cast<float4*>(out);
#pragma unroll
    for (int k = 0; k < W_ITERS; k++) {
        float m = __fdividef(sc[k].x, fmaxf(sc[k].y, 1.0f));
        o[tid + k * S] = make_float4(m, m, m, m);
    }
}

// ---------------------------------------------------------------------------
extern "C" void kernel_launch(void* const* d_in, const int* in_sizes, int n_in,
                              void* d_out, int out_size) {
    const float* vals = (const float*)d_in[0];   // [B, C, N] f32
    const int*   pix  = (const int*)d_in[1];     // [B, N] i32
    float*       out  = (float*)d_out;           // [B, NPIX, C] f32

    (void)in_sizes; (void)n_in; (void)out_size;

    {
        const int n = B * (NN / 8);              // 524288 threads
        accum_kernel<<<n / 256, 256>>>(vals, pix);
    }
    {
        write_kernel<<<W_THREADS / 256, 256>>>(out);
    }
}